// round 5
// baseline (speedup 1.0000x reference)
#include <cuda_runtime.h>
#include <math.h>

// Shapes (hardcoded from reference): B=16, N=32, C=8, O=16
// d_in order: x0, x1, x2, x3, W0, b0, W1, b1, W2, b2, W3, b3
// d_out: concat(out0[16,16], out1[16,32,16], out2[16,32,32,16], out3[16,32,32,32,16])

#define NB 16
#define NN 32

// Scratch (device globals — no runtime allocation)
__device__ float g_R3[NB * NN * NN * 16];   // reduce(x3): [b,a1,a2][max8|min8]
__device__ float g_T45[NB * NN * NN * 16];  // b3 + x2[b,j,k]·W3_p4 + x2[b,k,j]·W3_p5

__device__ __forceinline__ float sigm(float x) {
    return 1.0f / (1.0f + __expf(-x));
}

// ---------------------------------------------------------------------------
// Prep (small): T45 table only. grid 64 x 256 -> 16384 threads (b,j,k)
// ---------------------------------------------------------------------------
__global__ void __launch_bounds__(256) k_prepT45(
    const float* __restrict__ x2, const float* __restrict__ W3,
    const float* __restrict__ b3)
{
    int t = blockIdx.x * 256 + threadIdx.x;   // b,j,k
    int k = t & 31, j = (t >> 5) & 31, b = t >> 10;
    const float* pjk = x2 + ((b * 32 + j) * 32 + k) * 8;
    const float* pkj = x2 + ((b * 32 + k) * 32 + j) * 8;
    float acc[16];
    #pragma unroll
    for (int o = 0; o < 16; o++) acc[o] = b3[o];
    #pragma unroll
    for (int c = 0; c < 8; c++) {
        float v4 = pjk[c], v5 = pkj[c];
        #pragma unroll
        for (int o = 0; o < 16; o++)
            acc[o] += v4 * W3[(64 + c) * 16 + o] + v5 * W3[(80 + c) * 16 + o];
    }
    float4* dst = (float4*)(g_T45 + (size_t)t * 16);
    dst[0] = make_float4(acc[0], acc[1], acc[2], acc[3]);
    dst[1] = make_float4(acc[4], acc[5], acc[6], acc[7]);
    dst[2] = make_float4(acc[8], acc[9], acc[10], acc[11]);
    dst[3] = make_float4(acc[12], acc[13], acc[14], acc[15]);
}

// ---------------------------------------------------------------------------
// Main: out3 + R3. grid = B*N = 512 CTAs (b,i), 256 threads, dynamic smem.
//
// Smem slices (pitch 260 words/row, 8 words/col-chunk):
//   s1[a2][a3] = x3[b,i,a2,a3,:]   s2[a1][a3] = x3[b,a1,i,a3,:]
//   s3[a1][a2] = x3[b,a1,a2,i,:]
// Per position (j,k): 6 x3 terms = {s1[j][k], s1[k][j], s2[j][k], s2[k][j],
//                                   s3[j][k], s3[k][j]}, all LDS.
// logit = T45[b,j,k] + sA[j] + sC[k] + sum_t v_t . W_t
// R3[b,i,j,:] computed from s1 rows (masked max/min over a3).
// ---------------------------------------------------------------------------
#define PITCH 260
#define SLICE (32 * PITCH)      // 8320 floats
#define SM_S1 0
#define SM_S2 SLICE
#define SM_S3 (2 * SLICE)
#define SM_W  (3 * SLICE)               // 768 floats
#define SM_A  (3 * SLICE + 768)         // 512 floats
#define SM_C  (3 * SLICE + 1280)        // 512 floats
#define SM_FLOATS (3 * SLICE + 1792)    // 26752 floats = 107008 bytes

__global__ void __launch_bounds__(256, 2) k_main(
    const float* __restrict__ x2, const float* __restrict__ x3,
    const float* __restrict__ W3, float* __restrict__ out3)
{
    extern __shared__ __align__(16) float sm[];
    int blk = blockIdx.x;
    int b = blk >> 5;
    int i = blk & 31;
    int tid = threadIdx.x;

    const float* x3b = x3 + (size_t)b * 32 * 32 * 32 * 8;

    // ---- stage slices (coalesced float4) ----
    // s1: x3[b,i,:,:] — 2048 contiguous float4
    {
        const float4* src = (const float4*)(x3b + i * 8192);
        for (int idx = tid; idx < 2048; idx += 256) {
            int r = idx >> 6, w = idx & 63;
            *(float4*)(sm + SM_S1 + r * PITCH + w * 4) = src[idx];
        }
    }
    // s2: x3[b,a,i,:,:] — per a: 64 contiguous float4
    for (int idx = tid; idx < 2048; idx += 256) {
        int a = idx >> 6, w = idx & 63;
        float4 v = *(const float4*)(x3b + a * 8192 + i * 256 + w * 4);
        *(float4*)(sm + SM_S2 + a * PITCH + w * 4) = v;
    }
    // s3: x3[b,a1,a2,i,:] — 1024 chunks of 2 float4
    for (int idx = tid; idx < 2048; idx += 256) {
        int ch = idx >> 1, hf = idx & 1;
        int a1 = ch >> 5, a2 = ch & 31;
        float4 v = *(const float4*)(x3b + a1 * 8192 + a2 * 256 + i * 8 + hf * 4);
        *(float4*)(sm + SM_S3 + a1 * PITCH + a2 * 8 + hf * 4) = v;
    }
    // sW: x3-part weight blocks, rows 16*term+8+c of W3 -> [term][c][o]
    for (int idx = tid; idx < 768; idx += 256) {
        int term = idx >> 7;
        int r = idx & 127;
        int cc = r >> 4, o = r & 15;
        sm[SM_W + idx] = W3[(16 * term + 8 + cc) * 16 + o];
    }
    // sA[j][o], sC[k][o]: per-CTA x2-pair vectors
    {
        const float* x2b = x2 + (size_t)b * 32 * 32 * 8;
        for (int idx = tid; idx < 512; idx += 256) {
            int j = idx >> 4, o = idx & 15;
            float accA = 0.0f, accC = 0.0f;
            #pragma unroll
            for (int cc = 0; cc < 8; cc++) {
                float xij = x2b[(i * 32 + j) * 8 + cc];
                float xji = x2b[(j * 32 + i) * 8 + cc];
                accA += xij * W3[cc * 16 + o] + xji * W3[(32 + cc) * 16 + o];
                accC += xij * W3[(16 + cc) * 16 + o] + xji * W3[(48 + cc) * 16 + o];
            }
            sm[SM_A + idx] = accA;
            sm[SM_C + idx] = accC;
        }
    }
    __syncthreads();

    // ---- R3[b,i,j,:] from s1 (masked reduce over a3, exclude a3==j) ----
    {
        int j = tid >> 3, c = tid & 7;
        const float* row = sm + SM_S1 + j * PITCH + c;
        float vmax = -INFINITY, vmin = INFINITY;
        #pragma unroll
        for (int a = 0; a < 32; a++) {
            float v = row[a * 8];
            float vm = (a == j) ? 0.0f : v;
            float vn = (a == j) ? 1.0f : v;
            vmax = fmaxf(vmax, vm);
            vmin = fminf(vmin, vn);
        }
        int o = ((b * 32 + i) * 32 + j) * 16;
        g_R3[o + c] = vmax;
        g_R3[o + 8 + c] = vmin;
    }

    // ---- main compute ----
    int k = tid & 31, jb = tid >> 5;
    const float* sWp = sm + SM_W;

    #pragma unroll
    for (int it = 0; it < 2; it++) {
        int j0 = jb * 4 + it * 2;

        float acc[2][16];
        #pragma unroll
        for (int g = 0; g < 2; g++) {
            int j = j0 + g;
            const float4* t45 = (const float4*)(g_T45 + (((size_t)b * 32 + j) * 32 + k) * 16);
            const float4* pa = (const float4*)(sm + SM_A + j * 16);
            const float4* pc = (const float4*)(sm + SM_C + k * 16);
            #pragma unroll
            for (int q = 0; q < 4; q++) {
                float4 t = t45[q], a4 = pa[q], c4 = pc[q];
                acc[g][q * 4 + 0] = t.x + a4.x + c4.x;
                acc[g][q * 4 + 1] = t.y + a4.y + c4.y;
                acc[g][q * 4 + 2] = t.z + a4.z + c4.z;
                acc[g][q * 4 + 3] = t.w + a4.w + c4.w;
            }
        }

        #pragma unroll
        for (int term = 0; term < 6; term++) {
            // slice base + (row, col) per term: even terms (j,k), odd (k,j)
            int sl = (term >> 1) * SLICE;
            float v[2][8];
            #pragma unroll
            for (int g = 0; g < 2; g++) {
                int j = j0 + g;
                const float* p = (term & 1)
                    ? (sm + sl + k * PITCH + j * 8)
                    : (sm + sl + j * PITCH + k * 8);
                float4 lo = *(const float4*)p;
                float4 hi = *(const float4*)(p + 4);
                v[g][0] = lo.x; v[g][1] = lo.y; v[g][2] = lo.z; v[g][3] = lo.w;
                v[g][4] = hi.x; v[g][5] = hi.y; v[g][6] = hi.z; v[g][7] = hi.w;
            }
            const float* wt = sWp + term * 128;
            #pragma unroll
            for (int cc = 0; cc < 8; cc++) {
                float4 w0 = *(const float4*)(wt + cc * 16);
                float4 w1 = *(const float4*)(wt + cc * 16 + 4);
                float4 w2 = *(const float4*)(wt + cc * 16 + 8);
                float4 w3 = *(const float4*)(wt + cc * 16 + 12);
                #pragma unroll
                for (int g = 0; g < 2; g++) {
                    float s = v[g][cc];
                    acc[g][0]  += s * w0.x; acc[g][1]  += s * w0.y;
                    acc[g][2]  += s * w0.z; acc[g][3]  += s * w0.w;
                    acc[g][4]  += s * w1.x; acc[g][5]  += s * w1.y;
                    acc[g][6]  += s * w1.z; acc[g][7]  += s * w1.w;
                    acc[g][8]  += s * w2.x; acc[g][9]  += s * w2.y;
                    acc[g][10] += s * w2.z; acc[g][11] += s * w2.w;
                    acc[g][12] += s * w3.x; acc[g][13] += s * w3.y;
                    acc[g][14] += s * w3.z; acc[g][15] += s * w3.w;
                }
            }
        }

        #pragma unroll
        for (int g = 0; g < 2; g++) {
            int j = j0 + g;
            float4* dst = (float4*)(out3 + ((((size_t)b * 32 + i) * 32 + j) * 32 + k) * 16);
            #pragma unroll
            for (int q = 0; q < 4; q++) {
                float4 r;
                r.x = sigm(acc[g][q * 4 + 0]);
                r.y = sigm(acc[g][q * 4 + 1]);
                r.z = sigm(acc[g][q * 4 + 2]);
                r.w = sigm(acc[g][q * 4 + 3]);
                dst[q] = r;
            }
        }
    }
}

// ---------------------------------------------------------------------------
// Tail: out2 (blocks 0..63), out1 (64..65), out0 (66). Reads g_R3 (from k_main).
// ---------------------------------------------------------------------------
__global__ void __launch_bounds__(256) k_tail(
    const float* __restrict__ x0, const float* __restrict__ x1,
    const float* __restrict__ x2,
    const float* __restrict__ W0, const float* __restrict__ b0,
    const float* __restrict__ W1, const float* __restrict__ b1,
    const float* __restrict__ W2, const float* __restrict__ b2,
    float* __restrict__ out0, float* __restrict__ out1, float* __restrict__ out2)
{
    int blk = blockIdx.x, tid = threadIdx.x;
    if (blk < 64) {
        __shared__ __align__(16) float sW2[64 * 16];
        for (int idx = tid; idx < 1024; idx += 256) sW2[idx] = W2[idx];
        __syncthreads();

        int idx = blk * 256 + tid;  // b,i,j
        int j = idx & 31, i = (idx >> 5) & 31, b = idx >> 10;
        float f[64];
        const float* x1i = x1 + (b * 32 + i) * 8;
        const float* x1j = x1 + (b * 32 + j) * 8;
        const float* x2ij = x2 + ((b * 32 + i) * 32 + j) * 8;
        const float* x2ji = x2 + ((b * 32 + j) * 32 + i) * 8;
        const float* r3ij = g_R3 + ((b * 32 + i) * 32 + j) * 16;
        const float* r3ji = g_R3 + ((b * 32 + j) * 32 + i) * 16;
        #pragma unroll
        for (int c = 0; c < 8; c++) {
            f[c] = x1i[c];
            f[8 + c] = x2ij[c];
            f[32 + c] = x1j[c];
            f[40 + c] = x2ji[c];
        }
        #pragma unroll
        for (int c = 0; c < 16; c++) {
            f[16 + c] = r3ij[c];
            f[48 + c] = r3ji[c];
        }
        float acc[16];
        #pragma unroll
        for (int o = 0; o < 16; o++) acc[o] = b2[o];
        #pragma unroll
        for (int r = 0; r < 64; r++) {
            float4 w0 = *(const float4*)(sW2 + r * 16);
            float4 w1 = *(const float4*)(sW2 + r * 16 + 4);
            float4 w2 = *(const float4*)(sW2 + r * 16 + 8);
            float4 w3 = *(const float4*)(sW2 + r * 16 + 12);
            float s = f[r];
            acc[0]  += s * w0.x; acc[1]  += s * w0.y; acc[2]  += s * w0.z; acc[3]  += s * w0.w;
            acc[4]  += s * w1.x; acc[5]  += s * w1.y; acc[6]  += s * w1.z; acc[7]  += s * w1.w;
            acc[8]  += s * w2.x; acc[9]  += s * w2.y; acc[10] += s * w2.z; acc[11] += s * w2.w;
            acc[12] += s * w3.x; acc[13] += s * w3.y; acc[14] += s * w3.z; acc[15] += s * w3.w;
        }
        float* dst = out2 + (size_t)idx * 16;
        #pragma unroll
        for (int o = 0; o < 16; o++) dst[o] = sigm(acc[o]);
    } else if (blk < 66) {
        int idx = (blk - 64) * 256 + tid;
        if (idx < 512) {
            int b = idx >> 5, i = idx & 31;
            float f[32];
            #pragma unroll
            for (int c = 0; c < 8; c++) {
                f[c] = x0[b * 8 + c];
                f[8 + c] = x1[(b * 32 + i) * 8 + c];
            }
            // reduce(x2)[b,i]: max/min over axis=-2: x2[b,i,a,c], a==i masked
            #pragma unroll
            for (int c = 0; c < 8; c++) {
                float vmax = -INFINITY, vmin = INFINITY;
                for (int a = 0; a < 32; a++) {
                    float v = x2[((b * 32 + i) * 32 + a) * 8 + c];
                    float vm = (a == i) ? 0.0f : v;
                    float vn = (a == i) ? 1.0f : v;
                    vmax = fmaxf(vmax, vm);
                    vmin = fminf(vmin, vn);
                }
                f[16 + c] = vmax;
                f[24 + c] = vmin;
            }
            float acc[16];
            #pragma unroll
            for (int o = 0; o < 16; o++) acc[o] = b1[o];
            #pragma unroll
            for (int r = 0; r < 32; r++) {
                float s = f[r];
                #pragma unroll
                for (int o = 0; o < 16; o++) acc[o] += s * W1[r * 16 + o];
            }
            float* dst = out1 + (size_t)idx * 16;
            #pragma unroll
            for (int o = 0; o < 16; o++) dst[o] = sigm(acc[o]);
        }
    } else {
        int b = tid >> 4, o = tid & 15;
        float f[24];
        #pragma unroll
        for (int c = 0; c < 8; c++) f[c] = x0[b * 8 + c];
        // reduce(x1): no exclusion (ndim < 4 branch)
        #pragma unroll
        for (int c = 0; c < 8; c++) {
            float vmax = -INFINITY, vmin = INFINITY;
            for (int n = 0; n < 32; n++) {
                float v = x1[(b * 32 + n) * 8 + c];
                vmax = fmaxf(vmax, v);
                vmin = fminf(vmin, v);
            }
            f[8 + c] = vmax;
            f[16 + c] = vmin;
        }
        float acc = b0[o];
        #pragma unroll
        for (int r = 0; r < 24; r++) acc += f[r] * W0[r * 16 + o];
        out0[b * 16 + o] = sigm(acc);
    }
}

// ---------------------------------------------------------------------------
extern "C" void kernel_launch(void* const* d_in, const int* in_sizes, int n_in,
                              void* d_out, int out_size)
{
    const float* x0 = (const float*)d_in[0];
    const float* x1 = (const float*)d_in[1];
    const float* x2 = (const float*)d_in[2];
    const float* x3 = (const float*)d_in[3];
    const float* W0 = (const float*)d_in[4];
    const float* b0 = (const float*)d_in[5];
    const float* W1 = (const float*)d_in[6];
    const float* b1 = (const float*)d_in[7];
    const float* W2 = (const float*)d_in[8];
    const float* b2 = (const float*)d_in[9];
    const float* W3 = (const float*)d_in[10];
    const float* b3 = (const float*)d_in[11];

    float* out = (float*)d_out;
    float* out0 = out;                 // [16,16]            =     256
    float* out1 = out + 256;           // [16,32,16]         =    8192
    float* out2 = out + 8448;          // [16,32,32,16]      =  262144
    float* out3 = out + 270592;        // [16,32,32,32,16]   = 8388608

    const int smem_bytes = SM_FLOATS * 4;  // 107008
    cudaFuncSetAttribute(k_main, cudaFuncAttributeMaxDynamicSharedMemorySize, smem_bytes);

    k_prepT45<<<64, 256>>>(x2, W3, b3);
    k_main<<<512, 256, smem_bytes>>>(x2, x3, W3, out3);
    k_tail<<<67, 256>>>(x0, x1, x2, W0, b0, W1, b1, W2, b2, out0, out1, out2);
}

// round 6
// speedup vs baseline: 1.9453x; 1.9453x over previous
#include <cuda_runtime.h>
#include <math.h>

// Shapes (hardcoded from reference): B=16, N=32, C=8, O=16
// d_in order: x0, x1, x2, x3, W0, b0, W1, b1, W2, b2, W3, b3
// d_out: concat(out0[16,16], out1[16,32,16], out2[16,32,32,16], out3[16,32,32,32,16])

#define NB 16
#define NN 32

// Scratch (device globals — no runtime allocation)
__device__ float g_R3[NB * NN * NN * 16];   // reduce(x3): [b,a1,a2][max8|min8]
__device__ float g_T45[NB * NN * NN * 16];  // b3 + x2[b,j,k]·W3_p4 + x2[b,k,j]·W3_p5

__device__ __forceinline__ float sigm(float x) {
    return 1.0f / (1.0f + __expf(-x));
}

// ---------------------------------------------------------------------------
// Prep: T45 table. 65536 threads: (b,j,k,oq) — each computes one o-quad.
// ---------------------------------------------------------------------------
__global__ void __launch_bounds__(256) k_prepT45(
    const float* __restrict__ x2, const float* __restrict__ W3,
    const float* __restrict__ b3)
{
    int t = blockIdx.x * 256 + threadIdx.x;
    int q = t & 3, k = (t >> 2) & 31, j = (t >> 7) & 31, b = t >> 12;
    const float* pjk = x2 + ((b * 32 + j) * 32 + k) * 8;
    const float* pkj = x2 + ((b * 32 + k) * 32 + j) * 8;
    float a0 = b3[q * 4 + 0], a1 = b3[q * 4 + 1];
    float a2 = b3[q * 4 + 2], a3 = b3[q * 4 + 3];
    #pragma unroll
    for (int c = 0; c < 8; c++) {
        float v4 = pjk[c], v5 = pkj[c];
        const float* w4 = W3 + (64 + c) * 16 + q * 4;
        const float* w5 = W3 + (80 + c) * 16 + q * 4;
        a0 += v4 * w4[0] + v5 * w5[0];
        a1 += v4 * w4[1] + v5 * w5[1];
        a2 += v4 * w4[2] + v5 * w5[2];
        a3 += v4 * w4[3] + v5 * w5[3];
    }
    *(float4*)(g_T45 + ((size_t)(t >> 2)) * 16 + q * 4) = make_float4(a0, a1, a2, a3);
}

// ---------------------------------------------------------------------------
// Main: out3 + R3. grid = B*N*2 = 1024 CTAs (b,i,h), 256 threads, dyn smem.
//
// Smem slices (pitch 260 words/row, 8 words per (row,col) vector):
//   s1[a2][a3] = x3[b,i,a2,a3,:]   s2[a1][a3] = x3[b,a1,i,a3,:]
//   s3[a1][a2] = x3[b,a1,a2,i,:]
// Per position (j,k) the 6 permuted x3 vectors are
//   {s1[j][k], s1[k][j], s2[j][k], s2[k][j], s3[j][k], s3[k][j]}  (all LDS).
// logit = T45[b,j,k] + sA[j] + sC[k] + sum_t v_t . W_t
// R3[b,i,j,:] computed from s1 rows by h==0 CTAs.
// Thread: jb=tid>>5, k=tid&31; handles j = h*16 + jb*2 + {0,1}.
// ---------------------------------------------------------------------------
#define PITCH 260
#define SLICE (32 * PITCH)      // 8320 floats
#define SM_S1 0
#define SM_S2 SLICE
#define SM_S3 (2 * SLICE)
#define SM_W  (3 * SLICE)               // 768 floats
#define SM_A  (3 * SLICE + 768)         // 512 floats
#define SM_C  (3 * SLICE + 1280)        // 512 floats
#define SM_FLOATS (3 * SLICE + 1792)    // 26752 floats = 107008 bytes

__global__ void __launch_bounds__(256) k_main(
    const float* __restrict__ x2, const float* __restrict__ x3,
    const float* __restrict__ W3, float* __restrict__ out3)
{
    extern __shared__ __align__(16) float sm[];
    int blk = blockIdx.x;
    int b = blk >> 6;
    int i = (blk >> 1) & 31;
    int h = blk & 1;
    int tid = threadIdx.x;

    const float* x3b = x3 + (size_t)b * 32 * 32 * 32 * 8;

    // ---- stage slices (coalesced float4) ----
    {
        const float4* src = (const float4*)(x3b + i * 8192);
        for (int idx = tid; idx < 2048; idx += 256) {
            int r = idx >> 6, w = idx & 63;
            *(float4*)(sm + SM_S1 + r * PITCH + w * 4) = src[idx];
        }
    }
    for (int idx = tid; idx < 2048; idx += 256) {
        int a = idx >> 6, w = idx & 63;
        float4 v = *(const float4*)(x3b + a * 8192 + i * 256 + w * 4);
        *(float4*)(sm + SM_S2 + a * PITCH + w * 4) = v;
    }
    for (int idx = tid; idx < 2048; idx += 256) {
        int ch = idx >> 1, hf = idx & 1;
        int a1 = ch >> 5, a2 = ch & 31;
        float4 v = *(const float4*)(x3b + a1 * 8192 + a2 * 256 + i * 8 + hf * 4);
        *(float4*)(sm + SM_S3 + a1 * PITCH + a2 * 8 + hf * 4) = v;
    }
    // sW: x3-part weight blocks, rows 16*term+8+c of W3 -> [term][c][o]
    for (int idx = tid; idx < 768; idx += 256) {
        int term = idx >> 7;
        int r = idx & 127;
        int cc = r >> 4, o = r & 15;
        sm[SM_W + idx] = W3[(16 * term + 8 + cc) * 16 + o];
    }
    // sA[j][o], sC[k][o]: per-CTA x2-pair vectors
    {
        const float* x2b = x2 + (size_t)b * 32 * 32 * 8;
        for (int idx = tid; idx < 512; idx += 256) {
            int j = idx >> 4, o = idx & 15;
            float accA = 0.0f, accC = 0.0f;
            #pragma unroll
            for (int cc = 0; cc < 8; cc++) {
                float xij = x2b[(i * 32 + j) * 8 + cc];
                float xji = x2b[(j * 32 + i) * 8 + cc];
                accA += xij * W3[cc * 16 + o] + xji * W3[(32 + cc) * 16 + o];
                accC += xij * W3[(16 + cc) * 16 + o] + xji * W3[(48 + cc) * 16 + o];
            }
            sm[SM_A + idx] = accA;
            sm[SM_C + idx] = accC;
        }
    }
    __syncthreads();

    // ---- R3[b,i,j,:] from s1 (masked reduce over a3, exclude a3==j) — h==0 only
    if (h == 0) {
        int j = tid >> 3, c = tid & 7;
        const float* row = sm + SM_S1 + j * PITCH + c;
        float vmax = -INFINITY, vmin = INFINITY;
        #pragma unroll
        for (int a = 0; a < 32; a++) {
            float v = row[a * 8];
            float vm = (a == j) ? 0.0f : v;
            float vn = (a == j) ? 1.0f : v;
            vmax = fmaxf(vmax, vm);
            vmin = fminf(vmin, vn);
        }
        int o = ((b * 32 + i) * 32 + j) * 16;
        g_R3[o + c] = vmax;
        g_R3[o + 8 + c] = vmin;
    }

    // ---- main compute: 2 positions per thread ----
    int k = tid & 31, jb = tid >> 5;
    int j0 = h * 16 + jb * 2;
    const float* sWp = sm + SM_W;

    float acc[2][16];
    #pragma unroll
    for (int g = 0; g < 2; g++) {
        int j = j0 + g;
        const float4* t45 = (const float4*)(g_T45 + (((size_t)b * 32 + j) * 32 + k) * 16);
        const float4* pa = (const float4*)(sm + SM_A + j * 16);
        const float4* pc = (const float4*)(sm + SM_C + k * 16);
        #pragma unroll
        for (int q = 0; q < 4; q++) {
            float4 t = t45[q], a4 = pa[q], c4 = pc[q];
            acc[g][q * 4 + 0] = t.x + a4.x + c4.x;
            acc[g][q * 4 + 1] = t.y + a4.y + c4.y;
            acc[g][q * 4 + 2] = t.z + a4.z + c4.z;
            acc[g][q * 4 + 3] = t.w + a4.w + c4.w;
        }
    }

    #pragma unroll
    for (int term = 0; term < 6; term++) {
        int sl = (term >> 1) * SLICE;
        float v[2][8];
        #pragma unroll
        for (int g = 0; g < 2; g++) {
            int j = j0 + g;
            const float* p = (term & 1)
                ? (sm + sl + k * PITCH + j * 8)
                : (sm + sl + j * PITCH + k * 8);
            float4 lo = *(const float4*)p;
            float4 hi = *(const float4*)(p + 4);
            v[g][0] = lo.x; v[g][1] = lo.y; v[g][2] = lo.z; v[g][3] = lo.w;
            v[g][4] = hi.x; v[g][5] = hi.y; v[g][6] = hi.z; v[g][7] = hi.w;
        }
        const float* wt = sWp + term * 128;
        #pragma unroll
        for (int cc = 0; cc < 8; cc++) {
            float4 w0 = *(const float4*)(wt + cc * 16);
            float4 w1 = *(const float4*)(wt + cc * 16 + 4);
            float4 w2 = *(const float4*)(wt + cc * 16 + 8);
            float4 w3 = *(const float4*)(wt + cc * 16 + 12);
            #pragma unroll
            for (int g = 0; g < 2; g++) {
                float s = v[g][cc];
                acc[g][0]  += s * w0.x; acc[g][1]  += s * w0.y;
                acc[g][2]  += s * w0.z; acc[g][3]  += s * w0.w;
                acc[g][4]  += s * w1.x; acc[g][5]  += s * w1.y;
                acc[g][6]  += s * w1.z; acc[g][7]  += s * w1.w;
                acc[g][8]  += s * w2.x; acc[g][9]  += s * w2.y;
                acc[g][10] += s * w2.z; acc[g][11] += s * w2.w;
                acc[g][12] += s * w3.x; acc[g][13] += s * w3.y;
                acc[g][14] += s * w3.z; acc[g][15] += s * w3.w;
            }
        }
    }

    #pragma unroll
    for (int g = 0; g < 2; g++) {
        int j = j0 + g;
        float4* dst = (float4*)(out3 + ((((size_t)b * 32 + i) * 32 + j) * 32 + k) * 16);
        #pragma unroll
        for (int q = 0; q < 4; q++) {
            float4 r;
            r.x = sigm(acc[g][q * 4 + 0]);
            r.y = sigm(acc[g][q * 4 + 1]);
            r.z = sigm(acc[g][q * 4 + 2]);
            r.w = sigm(acc[g][q * 4 + 3]);
            dst[q] = r;
        }
    }
}

// ---------------------------------------------------------------------------
// Tail: out2 (blocks 0..63), out1 (64..65), out0 (66). Reads g_R3 (from k_main).
// ---------------------------------------------------------------------------
__global__ void __launch_bounds__(256) k_tail(
    const float* __restrict__ x0, const float* __restrict__ x1,
    const float* __restrict__ x2,
    const float* __restrict__ W0, const float* __restrict__ b0,
    const float* __restrict__ W1, const float* __restrict__ b1,
    const float* __restrict__ W2, const float* __restrict__ b2,
    float* __restrict__ out0, float* __restrict__ out1, float* __restrict__ out2)
{
    int blk = blockIdx.x, tid = threadIdx.x;
    if (blk < 64) {
        __shared__ __align__(16) float sW2[64 * 16];
        for (int idx = tid; idx < 1024; idx += 256) sW2[idx] = W2[idx];
        __syncthreads();

        int idx = blk * 256 + tid;  // b,i,j
        int j = idx & 31, i = (idx >> 5) & 31, b = idx >> 10;
        float f[64];
        const float* x1i = x1 + (b * 32 + i) * 8;
        const float* x1j = x1 + (b * 32 + j) * 8;
        const float* x2ij = x2 + ((b * 32 + i) * 32 + j) * 8;
        const float* x2ji = x2 + ((b * 32 + j) * 32 + i) * 8;
        const float* r3ij = g_R3 + ((b * 32 + i) * 32 + j) * 16;
        const float* r3ji = g_R3 + ((b * 32 + j) * 32 + i) * 16;
        #pragma unroll
        for (int c = 0; c < 8; c++) {
            f[c] = x1i[c];
            f[8 + c] = x2ij[c];
            f[32 + c] = x1j[c];
            f[40 + c] = x2ji[c];
        }
        #pragma unroll
        for (int c = 0; c < 16; c++) {
            f[16 + c] = r3ij[c];
            f[48 + c] = r3ji[c];
        }
        float acc[16];
        #pragma unroll
        for (int o = 0; o < 16; o++) acc[o] = b2[o];
        #pragma unroll
        for (int r = 0; r < 64; r++) {
            float4 w0 = *(const float4*)(sW2 + r * 16);
            float4 w1 = *(const float4*)(sW2 + r * 16 + 4);
            float4 w2 = *(const float4*)(sW2 + r * 16 + 8);
            float4 w3 = *(const float4*)(sW2 + r * 16 + 12);
            float s = f[r];
            acc[0]  += s * w0.x; acc[1]  += s * w0.y; acc[2]  += s * w0.z; acc[3]  += s * w0.w;
            acc[4]  += s * w1.x; acc[5]  += s * w1.y; acc[6]  += s * w1.z; acc[7]  += s * w1.w;
            acc[8]  += s * w2.x; acc[9]  += s * w2.y; acc[10] += s * w2.z; acc[11] += s * w2.w;
            acc[12] += s * w3.x; acc[13] += s * w3.y; acc[14] += s * w3.z; acc[15] += s * w3.w;
        }
        float* dst = out2 + (size_t)idx * 16;
        #pragma unroll
        for (int o = 0; o < 16; o++) dst[o] = sigm(acc[o]);
    } else if (blk < 66) {
        int idx = (blk - 64) * 256 + tid;
        if (idx < 512) {
            int b = idx >> 5, i = idx & 31;
            float f[32];
            #pragma unroll
            for (int c = 0; c < 8; c++) {
                f[c] = x0[b * 8 + c];
                f[8 + c] = x1[(b * 32 + i) * 8 + c];
            }
            // reduce(x2)[b,i]: max/min over axis=-2: x2[b,i,a,c], a==i masked
            #pragma unroll
            for (int c = 0; c < 8; c++) {
                float vmax = -INFINITY, vmin = INFINITY;
                for (int a = 0; a < 32; a++) {
                    float v = x2[((b * 32 + i) * 32 + a) * 8 + c];
                    float vm = (a == i) ? 0.0f : v;
                    float vn = (a == i) ? 1.0f : v;
                    vmax = fmaxf(vmax, vm);
                    vmin = fminf(vmin, vn);
                }
                f[16 + c] = vmax;
                f[24 + c] = vmin;
            }
            float acc[16];
            #pragma unroll
            for (int o = 0; o < 16; o++) acc[o] = b1[o];
            #pragma unroll
            for (int r = 0; r < 32; r++) {
                float s = f[r];
                #pragma unroll
                for (int o = 0; o < 16; o++) acc[o] += s * W1[r * 16 + o];
            }
            float* dst = out1 + (size_t)idx * 16;
            #pragma unroll
            for (int o = 0; o < 16; o++) dst[o] = sigm(acc[o]);
        }
    } else {
        int b = tid >> 4, o = tid & 15;
        float f[24];
        #pragma unroll
        for (int c = 0; c < 8; c++) f[c] = x0[b * 8 + c];
        // reduce(x1): no exclusion (ndim < 4 branch)
        #pragma unroll
        for (int c = 0; c < 8; c++) {
            float vmax = -INFINITY, vmin = INFINITY;
            for (int n = 0; n < 32; n++) {
                float v = x1[(b * 32 + n) * 8 + c];
                vmax = fmaxf(vmax, v);
                vmin = fminf(vmin, v);
            }
            f[8 + c] = vmax;
            f[16 + c] = vmin;
        }
        float acc = b0[o];
        #pragma unroll
        for (int r = 0; r < 24; r++) acc += f[r] * W0[r * 16 + o];
        out0[b * 16 + o] = sigm(acc);
    }
}

// ---------------------------------------------------------------------------
extern "C" void kernel_launch(void* const* d_in, const int* in_sizes, int n_in,
                              void* d_out, int out_size)
{
    const float* x0 = (const float*)d_in[0];
    const float* x1 = (const float*)d_in[1];
    const float* x2 = (const float*)d_in[2];
    const float* x3 = (const float*)d_in[3];
    const float* W0 = (const float*)d_in[4];
    const float* b0 = (const float*)d_in[5];
    const float* W1 = (const float*)d_in[6];
    const float* b1 = (const float*)d_in[7];
    const float* W2 = (const float*)d_in[8];
    const float* b2 = (const float*)d_in[9];
    const float* W3 = (const float*)d_in[10];
    const float* b3 = (const float*)d_in[11];

    float* out = (float*)d_out;
    float* out0 = out;                 // [16,16]            =     256
    float* out1 = out + 256;           // [16,32,16]         =    8192
    float* out2 = out + 8448;          // [16,32,32,16]      =  262144
    float* out3 = out + 270592;        // [16,32,32,32,16]   = 8388608

    const int smem_bytes = SM_FLOATS * 4;  // 107008
    cudaFuncSetAttribute(k_main, cudaFuncAttributeMaxDynamicSharedMemorySize, smem_bytes);

    k_prepT45<<<256, 256>>>(x2, W3, b3);
    k_main<<<1024, 256, smem_bytes>>>(x2, x3, W3, out3);
    k_tail<<<67, 256>>>(x0, x1, x2, W0, b0, W1, b1, W2, b2, out0, out1, out2);
}

// round 7
// speedup vs baseline: 2.0422x; 1.0498x over previous
#include <cuda_runtime.h>
#include <math.h>

// Shapes (hardcoded from reference): B=16, N=32, C=8, O=16
// d_in order: x0, x1, x2, x3, W0, b0, W1, b1, W2, b2, W3, b3
// d_out: concat(out0[16,16], out1[16,32,16], out2[16,32,32,16], out3[16,32,32,32,16])

#define NB 16
#define NN 32

// Scratch (device global — no runtime allocation)
__device__ float g_R3[NB * NN * NN * 16];   // reduce(x3): [b,a1,a2][max8|min8]

__device__ __forceinline__ float sigm(float x) {
    return __fdividef(1.0f, 1.0f + __expf(-x));
}

// ---------------------------------------------------------------------------
// Main: out3 + R3, self-contained (no prep dependency -> first graph node).
// grid = B*N*2 = 1024 CTAs (b,i,h), 256 threads.
// Thread: jb=tid>>5, k=tid&31; handles j = h*16 + jb*2 + {0,1}.
// logit[j,k,:] = b3 + sA[j] + sC[k]
//             + x2[b,j,k]·W3[64:72] + x2[b,k,j]·W3[80:88]     (inline "T45")
//             + sum_{t=0..5} x3[perm_t(i,j,k)]·W3[16t+8:16t+16] (global gather)
// R3[b,i,:, :] written by h==0 CTAs (masked max/min over a3).
// ---------------------------------------------------------------------------
__global__ void __launch_bounds__(256) k_main(
    const float* __restrict__ x2, const float* __restrict__ x3,
    const float* __restrict__ W3, const float* __restrict__ b3,
    float* __restrict__ out3)
{
    __shared__ __align__(16) float sX2[32 * 32 * 8];  // x2[b] slice, 32KB
    __shared__ __align__(16) float sW3[96 * 16];      // full W3, 6KB
    __shared__ __align__(16) float sB3[16];
    __shared__ __align__(16) float sA[32 * 16];       // p0+p2 x2-terms
    __shared__ __align__(16) float sC[32 * 16];       // p1+p3 x2-terms

    int blk = blockIdx.x;
    int b = blk >> 6;
    int i = (blk >> 1) & 31;
    int h = blk & 1;
    int tid = threadIdx.x;

    // ---- stage x2[b] + W3 + b3 (coalesced) ----
    {
        const float4* src = (const float4*)(x2 + (size_t)b * 8192);
        float4* dst = (float4*)sX2;
        for (int idx = tid; idx < 2048; idx += 256) dst[idx] = src[idx];
    }
    {
        const float4* src = (const float4*)W3;
        float4* dst = (float4*)sW3;
        for (int idx = tid; idx < 384; idx += 256) dst[idx] = src[idx];
    }
    if (tid < 16) sB3[tid] = b3[tid];
    __syncthreads();

    // ---- sA[j][o], sC[k][o] from sX2 ----
    for (int idx = tid; idx < 512; idx += 256) {
        int j = idx >> 4, o = idx & 15;
        float accA = 0.0f, accC = 0.0f;
        #pragma unroll
        for (int cc = 0; cc < 8; cc++) {
            float xij = sX2[(i * 32 + j) * 8 + cc];
            float xji = sX2[(j * 32 + i) * 8 + cc];
            accA += xij * sW3[cc * 16 + o] + xji * sW3[(32 + cc) * 16 + o];
            accC += xij * sW3[(16 + cc) * 16 + o] + xji * sW3[(48 + cc) * 16 + o];
        }
        sA[idx] = accA;
        sC[idx] = accC;
    }
    __syncthreads();

    const float* x3b = x3 + (size_t)b * 32 * 32 * 32 * 8;

    // ---- R3[b,i,j,:] (h==0 CTAs): masked reduce over a3, exclude a3==j ----
    if (h == 0) {
        int j = tid >> 3, c = tid & 7;
        const float* p = x3b + ((i * 32 + j) * 32) * 8 + c;
        float vmax = -INFINITY, vmin = INFINITY;
        #pragma unroll 8
        for (int a = 0; a < 32; a++) {
            float v = p[a * 8];
            float vm = (a == j) ? 0.0f : v;
            float vn = (a == j) ? 1.0f : v;
            vmax = fmaxf(vmax, vm);
            vmin = fminf(vmin, vn);
        }
        int o = ((b * 32 + i) * 32 + j) * 16;
        g_R3[o + c] = vmax;
        g_R3[o + 8 + c] = vmin;
    }

    // ---- main compute: 2 positions per thread ----
    int k = tid & 31, jb = tid >> 5;
    int j0 = h * 16 + jb * 2;

    float acc[2][16];
    #pragma unroll
    for (int g = 0; g < 2; g++) {
        int j = j0 + g;
        const float* pa = sA + j * 16;
        const float* pc = sC + k * 16;
        #pragma unroll
        for (int o = 0; o < 16; o++) acc[g][o] = sB3[o] + pa[o] + pc[o];
        // inline T45: x2[b,j,k]·W3[64:72] + x2[b,k,j]·W3[80:88]
        const float* xjk = sX2 + (j * 32 + k) * 8;
        const float* xkj = sX2 + (k * 32 + j) * 8;
        #pragma unroll
        for (int cc = 0; cc < 8; cc++) {
            float v4 = xjk[cc], v5 = xkj[cc];
            const float* w4 = sW3 + (64 + cc) * 16;
            const float* w5 = sW3 + (80 + cc) * 16;
            #pragma unroll
            for (int o = 0; o < 16; o++)
                acc[g][o] += v4 * w4[o] + v5 * w5[o];
        }
    }

    // gather offsets (floats): x3[b,a1,a2,a3,c] -> a1*8192 + a2*256 + a3*8
    int iS1 = i * 8192, iS2 = i * 256, iS3 = i * 8;
    int kS1 = k * 8192, kS2 = k * 256, kS3 = k * 8;
    int offs[2][6];
    #pragma unroll
    for (int g = 0; g < 2; g++) {
        int j = j0 + g;
        int jS1 = j * 8192, jS2 = j * 256, jS3 = j * 8;
        offs[g][0] = iS1 + jS2 + kS3;  // x3[b,i,j,k]  rows  8..15
        offs[g][1] = iS1 + kS2 + jS3;  // x3[b,i,k,j]  rows 24..31
        offs[g][2] = jS1 + iS2 + kS3;  // x3[b,j,i,k]  rows 40..47
        offs[g][3] = kS1 + iS2 + jS3;  // x3[b,k,i,j]  rows 56..63
        offs[g][4] = jS1 + kS2 + iS3;  // x3[b,j,k,i]  rows 72..79
        offs[g][5] = kS1 + jS2 + iS3;  // x3[b,k,j,i]  rows 88..95
    }

    #pragma unroll
    for (int term = 0; term < 6; term++) {
        float v[2][8];
        #pragma unroll
        for (int g = 0; g < 2; g++) {
            const float* p = x3b + offs[g][term];
            float4 lo = *(const float4*)p;
            float4 hi = *(const float4*)(p + 4);
            v[g][0] = lo.x; v[g][1] = lo.y; v[g][2] = lo.z; v[g][3] = lo.w;
            v[g][4] = hi.x; v[g][5] = hi.y; v[g][6] = hi.z; v[g][7] = hi.w;
        }
        const float* wt = sW3 + (16 * term + 8) * 16;
        #pragma unroll
        for (int cc = 0; cc < 8; cc++) {
            float4 w0 = *(const float4*)(wt + cc * 16);
            float4 w1 = *(const float4*)(wt + cc * 16 + 4);
            float4 w2 = *(const float4*)(wt + cc * 16 + 8);
            float4 w3 = *(const float4*)(wt + cc * 16 + 12);
            #pragma unroll
            for (int g = 0; g < 2; g++) {
                float s = v[g][cc];
                acc[g][0]  += s * w0.x; acc[g][1]  += s * w0.y;
                acc[g][2]  += s * w0.z; acc[g][3]  += s * w0.w;
                acc[g][4]  += s * w1.x; acc[g][5]  += s * w1.y;
                acc[g][6]  += s * w1.z; acc[g][7]  += s * w1.w;
                acc[g][8]  += s * w2.x; acc[g][9]  += s * w2.y;
                acc[g][10] += s * w2.z; acc[g][11] += s * w2.w;
                acc[g][12] += s * w3.x; acc[g][13] += s * w3.y;
                acc[g][14] += s * w3.z; acc[g][15] += s * w3.w;
            }
        }
    }

    #pragma unroll
    for (int g = 0; g < 2; g++) {
        int j = j0 + g;
        float4* dst = (float4*)(out3 + ((((size_t)b * 32 + i) * 32 + j) * 32 + k) * 16);
        #pragma unroll
        for (int q = 0; q < 4; q++) {
            float4 r;
            r.x = sigm(acc[g][q * 4 + 0]);
            r.y = sigm(acc[g][q * 4 + 1]);
            r.z = sigm(acc[g][q * 4 + 2]);
            r.w = sigm(acc[g][q * 4 + 3]);
            dst[q] = r;
        }
    }
}

// ---------------------------------------------------------------------------
// Tail: out2 (blocks 0..63), out1 (64..65), out0 (66). Reads g_R3 (from k_main).
// ---------------------------------------------------------------------------
__global__ void __launch_bounds__(256) k_tail(
    const float* __restrict__ x0, const float* __restrict__ x1,
    const float* __restrict__ x2,
    const float* __restrict__ W0, const float* __restrict__ b0,
    const float* __restrict__ W1, const float* __restrict__ b1,
    const float* __restrict__ W2, const float* __restrict__ b2,
    float* __restrict__ out0, float* __restrict__ out1, float* __restrict__ out2)
{
    int blk = blockIdx.x, tid = threadIdx.x;
    if (blk < 64) {
        __shared__ __align__(16) float sW2[64 * 16];
        for (int idx = tid; idx < 1024; idx += 256) sW2[idx] = W2[idx];
        __syncthreads();

        int idx = blk * 256 + tid;  // b,i,j
        int j = idx & 31, i = (idx >> 5) & 31, b = idx >> 10;
        float f[64];
        const float* x1i = x1 + (b * 32 + i) * 8;
        const float* x1j = x1 + (b * 32 + j) * 8;
        const float* x2ij = x2 + ((b * 32 + i) * 32 + j) * 8;
        const float* x2ji = x2 + ((b * 32 + j) * 32 + i) * 8;
        const float* r3ij = g_R3 + ((b * 32 + i) * 32 + j) * 16;
        const float* r3ji = g_R3 + ((b * 32 + j) * 32 + i) * 16;
        #pragma unroll
        for (int c = 0; c < 8; c++) {
            f[c] = x1i[c];
            f[8 + c] = x2ij[c];
            f[32 + c] = x1j[c];
            f[40 + c] = x2ji[c];
        }
        #pragma unroll
        for (int c = 0; c < 16; c++) {
            f[16 + c] = r3ij[c];
            f[48 + c] = r3ji[c];
        }
        float acc[16];
        #pragma unroll
        for (int o = 0; o < 16; o++) acc[o] = b2[o];
        #pragma unroll
        for (int r = 0; r < 64; r++) {
            float4 w0 = *(const float4*)(sW2 + r * 16);
            float4 w1 = *(const float4*)(sW2 + r * 16 + 4);
            float4 w2 = *(const float4*)(sW2 + r * 16 + 8);
            float4 w3 = *(const float4*)(sW2 + r * 16 + 12);
            float s = f[r];
            acc[0]  += s * w0.x; acc[1]  += s * w0.y; acc[2]  += s * w0.z; acc[3]  += s * w0.w;
            acc[4]  += s * w1.x; acc[5]  += s * w1.y; acc[6]  += s * w1.z; acc[7]  += s * w1.w;
            acc[8]  += s * w2.x; acc[9]  += s * w2.y; acc[10] += s * w2.z; acc[11] += s * w2.w;
            acc[12] += s * w3.x; acc[13] += s * w3.y; acc[14] += s * w3.z; acc[15] += s * w3.w;
        }
        float* dst = out2 + (size_t)idx * 16;
        #pragma unroll
        for (int o = 0; o < 16; o++) dst[o] = sigm(acc[o]);
    } else if (blk < 66) {
        int idx = (blk - 64) * 256 + tid;
        if (idx < 512) {
            int b = idx >> 5, i = idx & 31;
            float f[32];
            #pragma unroll
            for (int c = 0; c < 8; c++) {
                f[c] = x0[b * 8 + c];
                f[8 + c] = x1[(b * 32 + i) * 8 + c];
            }
            // reduce(x2)[b,i]: max/min over axis=-2: x2[b,i,a,c], a==i masked
            #pragma unroll
            for (int c = 0; c < 8; c++) {
                float vmax = -INFINITY, vmin = INFINITY;
                for (int a = 0; a < 32; a++) {
                    float v = x2[((b * 32 + i) * 32 + a) * 8 + c];
                    float vm = (a == i) ? 0.0f : v;
                    float vn = (a == i) ? 1.0f : v;
                    vmax = fmaxf(vmax, vm);
                    vmin = fminf(vmin, vn);
                }
                f[16 + c] = vmax;
                f[24 + c] = vmin;
            }
            float acc[16];
            #pragma unroll
            for (int o = 0; o < 16; o++) acc[o] = b1[o];
            #pragma unroll
            for (int r = 0; r < 32; r++) {
                float s = f[r];
                #pragma unroll
                for (int o = 0; o < 16; o++) acc[o] += s * W1[r * 16 + o];
            }
            float* dst = out1 + (size_t)idx * 16;
            #pragma unroll
            for (int o = 0; o < 16; o++) dst[o] = sigm(acc[o]);
        }
    } else {
        int b = tid >> 4, o = tid & 15;
        float f[24];
        #pragma unroll
        for (int c = 0; c < 8; c++) f[c] = x0[b * 8 + c];
        // reduce(x1): no exclusion (ndim < 4 branch)
        #pragma unroll
        for (int c = 0; c < 8; c++) {
            float vmax = -INFINITY, vmin = INFINITY;
            for (int n = 0; n < 32; n++) {
                float v = x1[(b * 32 + n) * 8 + c];
                vmax = fmaxf(vmax, v);
                vmin = fminf(vmin, v);
            }
            f[8 + c] = vmax;
            f[16 + c] = vmin;
        }
        float acc = b0[o];
        #pragma unroll
        for (int r = 0; r < 24; r++) acc += f[r] * W0[r * 16 + o];
        out0[b * 16 + o] = sigm(acc);
    }
}

// ---------------------------------------------------------------------------
extern "C" void kernel_launch(void* const* d_in, const int* in_sizes, int n_in,
                              void* d_out, int out_size)
{
    const float* x0 = (const float*)d_in[0];
    const float* x1 = (const float*)d_in[1];
    const float* x2 = (const float*)d_in[2];
    const float* x3 = (const float*)d_in[3];
    const float* W0 = (const float*)d_in[4];
    const float* b0 = (const float*)d_in[5];
    const float* W1 = (const float*)d_in[6];
    const float* b1 = (const float*)d_in[7];
    const float* W2 = (const float*)d_in[8];
    const float* b2 = (const float*)d_in[9];
    const float* W3 = (const float*)d_in[10];
    const float* b3 = (const float*)d_in[11];

    float* out = (float*)d_out;
    float* out0 = out;                 // [16,16]            =     256
    float* out1 = out + 256;           // [16,32,16]         =    8192
    float* out2 = out + 8448;          // [16,32,32,16]      =  262144
    float* out3 = out + 270592;        // [16,32,32,32,16]   = 8388608

    k_main<<<1024, 256>>>(x2, x3, W3, b3, out3);
    k_tail<<<67, 256>>>(x0, x1, x2, W0, b0, W1, b1, W2, b2, out0, out1, out2);
}

// round 8
// speedup vs baseline: 3.1401x; 1.5376x over previous
#include <cuda_runtime.h>
#include <math.h>

// Shapes (hardcoded from reference): B=16, N=32, C=8, O=16
// d_in order: x0, x1, x2, x3, W0, b0, W1, b1, W2, b2, W3, b3
// d_out: concat(out0[16,16], out1[16,32,16], out2[16,32,32,16], out3[16,32,32,32,16])

#define NB 16
#define NN 32

// Scratch (device global — no runtime allocation)
__device__ float g_R3[NB * NN * NN * 16];   // reduce(x3): [b,a1,a2][max8|min8]

__device__ __forceinline__ float sigm(float x) {
    return __fdividef(1.0f, 1.0f + __expf(-x));
}

// ---------------------------------------------------------------------------
// Main: out3 + R3 (unchanged from R7 — best measured, ~54us).
// grid = B*N*2 = 1024 CTAs (b,i,h), 256 threads.
// ---------------------------------------------------------------------------
__global__ void __launch_bounds__(256) k_main(
    const float* __restrict__ x2, const float* __restrict__ x3,
    const float* __restrict__ W3, const float* __restrict__ b3,
    float* __restrict__ out3)
{
    __shared__ __align__(16) float sX2[32 * 32 * 8];  // x2[b] slice, 32KB
    __shared__ __align__(16) float sW3[96 * 16];      // full W3, 6KB
    __shared__ __align__(16) float sB3[16];
    __shared__ __align__(16) float sA[32 * 16];       // p0+p2 x2-terms
    __shared__ __align__(16) float sC[32 * 16];       // p1+p3 x2-terms

    int blk = blockIdx.x;
    int b = blk >> 6;
    int i = (blk >> 1) & 31;
    int h = blk & 1;
    int tid = threadIdx.x;

    // ---- stage x2[b] + W3 + b3 (coalesced) ----
    {
        const float4* src = (const float4*)(x2 + (size_t)b * 8192);
        float4* dst = (float4*)sX2;
        for (int idx = tid; idx < 2048; idx += 256) dst[idx] = src[idx];
    }
    {
        const float4* src = (const float4*)W3;
        float4* dst = (float4*)sW3;
        for (int idx = tid; idx < 384; idx += 256) dst[idx] = src[idx];
    }
    if (tid < 16) sB3[tid] = b3[tid];
    __syncthreads();

    // ---- sA[j][o], sC[k][o] from sX2 ----
    for (int idx = tid; idx < 512; idx += 256) {
        int j = idx >> 4, o = idx & 15;
        float accA = 0.0f, accC = 0.0f;
        #pragma unroll
        for (int cc = 0; cc < 8; cc++) {
            float xij = sX2[(i * 32 + j) * 8 + cc];
            float xji = sX2[(j * 32 + i) * 8 + cc];
            accA += xij * sW3[cc * 16 + o] + xji * sW3[(32 + cc) * 16 + o];
            accC += xij * sW3[(16 + cc) * 16 + o] + xji * sW3[(48 + cc) * 16 + o];
        }
        sA[idx] = accA;
        sC[idx] = accC;
    }
    __syncthreads();

    const float* x3b = x3 + (size_t)b * 32 * 32 * 32 * 8;

    // ---- R3[b,i,j,:] (h==0 CTAs): masked reduce over a3, exclude a3==j ----
    if (h == 0) {
        int j = tid >> 3, c = tid & 7;
        const float* p = x3b + ((i * 32 + j) * 32) * 8 + c;
        float vmax = -INFINITY, vmin = INFINITY;
        #pragma unroll 8
        for (int a = 0; a < 32; a++) {
            float v = p[a * 8];
            float vm = (a == j) ? 0.0f : v;
            float vn = (a == j) ? 1.0f : v;
            vmax = fmaxf(vmax, vm);
            vmin = fminf(vmin, vn);
        }
        int o = ((b * 32 + i) * 32 + j) * 16;
        g_R3[o + c] = vmax;
        g_R3[o + 8 + c] = vmin;
    }

    // ---- main compute: 2 positions per thread ----
    int k = tid & 31, jb = tid >> 5;
    int j0 = h * 16 + jb * 2;

    float acc[2][16];
    #pragma unroll
    for (int g = 0; g < 2; g++) {
        int j = j0 + g;
        const float* pa = sA + j * 16;
        const float* pc = sC + k * 16;
        #pragma unroll
        for (int o = 0; o < 16; o++) acc[g][o] = sB3[o] + pa[o] + pc[o];
        // inline T45: x2[b,j,k]·W3[64:72] + x2[b,k,j]·W3[80:88]
        const float* xjk = sX2 + (j * 32 + k) * 8;
        const float* xkj = sX2 + (k * 32 + j) * 8;
        #pragma unroll
        for (int cc = 0; cc < 8; cc++) {
            float v4 = xjk[cc], v5 = xkj[cc];
            const float* w4 = sW3 + (64 + cc) * 16;
            const float* w5 = sW3 + (80 + cc) * 16;
            #pragma unroll
            for (int o = 0; o < 16; o++)
                acc[g][o] += v4 * w4[o] + v5 * w5[o];
        }
    }

    // gather offsets (floats): x3[b,a1,a2,a3,c] -> a1*8192 + a2*256 + a3*8
    int iS1 = i * 8192, iS2 = i * 256, iS3 = i * 8;
    int kS1 = k * 8192, kS2 = k * 256, kS3 = k * 8;
    int offs[2][6];
    #pragma unroll
    for (int g = 0; g < 2; g++) {
        int j = j0 + g;
        int jS1 = j * 8192, jS2 = j * 256, jS3 = j * 8;
        offs[g][0] = iS1 + jS2 + kS3;  // x3[b,i,j,k]  rows  8..15
        offs[g][1] = iS1 + kS2 + jS3;  // x3[b,i,k,j]  rows 24..31
        offs[g][2] = jS1 + iS2 + kS3;  // x3[b,j,i,k]  rows 40..47
        offs[g][3] = kS1 + iS2 + jS3;  // x3[b,k,i,j]  rows 56..63
        offs[g][4] = jS1 + kS2 + iS3;  // x3[b,j,k,i]  rows 72..79
        offs[g][5] = kS1 + jS2 + iS3;  // x3[b,k,j,i]  rows 88..95
    }

    #pragma unroll
    for (int term = 0; term < 6; term++) {
        float v[2][8];
        #pragma unroll
        for (int g = 0; g < 2; g++) {
            const float* p = x3b + offs[g][term];
            float4 lo = *(const float4*)p;
            float4 hi = *(const float4*)(p + 4);
            v[g][0] = lo.x; v[g][1] = lo.y; v[g][2] = lo.z; v[g][3] = lo.w;
            v[g][4] = hi.x; v[g][5] = hi.y; v[g][6] = hi.z; v[g][7] = hi.w;
        }
        const float* wt = sW3 + (16 * term + 8) * 16;
        #pragma unroll
        for (int cc = 0; cc < 8; cc++) {
            float4 w0 = *(const float4*)(wt + cc * 16);
            float4 w1 = *(const float4*)(wt + cc * 16 + 4);
            float4 w2 = *(const float4*)(wt + cc * 16 + 8);
            float4 w3 = *(const float4*)(wt + cc * 16 + 12);
            #pragma unroll
            for (int g = 0; g < 2; g++) {
                float s = v[g][cc];
                acc[g][0]  += s * w0.x; acc[g][1]  += s * w0.y;
                acc[g][2]  += s * w0.z; acc[g][3]  += s * w0.w;
                acc[g][4]  += s * w1.x; acc[g][5]  += s * w1.y;
                acc[g][6]  += s * w1.z; acc[g][7]  += s * w1.w;
                acc[g][8]  += s * w2.x; acc[g][9]  += s * w2.y;
                acc[g][10] += s * w2.z; acc[g][11] += s * w2.w;
                acc[g][12] += s * w3.x; acc[g][13] += s * w3.y;
                acc[g][14] += s * w3.z; acc[g][15] += s * w3.w;
            }
        }
    }

    #pragma unroll
    for (int g = 0; g < 2; g++) {
        int j = j0 + g;
        float4* dst = (float4*)(out3 + ((((size_t)b * 32 + i) * 32 + j) * 32 + k) * 16);
        #pragma unroll
        for (int q = 0; q < 4; q++) {
            float4 r;
            r.x = sigm(acc[g][q * 4 + 0]);
            r.y = sigm(acc[g][q * 4 + 1]);
            r.z = sigm(acc[g][q * 4 + 2]);
            r.w = sigm(acc[g][q * 4 + 3]);
            dst[q] = r;
        }
    }
}

// ---------------------------------------------------------------------------
// Tail v2 — spill-free, wide.
//   blocks [0,128): out2 — 2 threads per (b,i,j), 8 outputs each, acc-only
//   blocks [128,144): out1 — one CTA per b; phase1 smem reduce, phase2 matmul
//   block 144: out0
// ---------------------------------------------------------------------------
__global__ void __launch_bounds__(256) k_tail(
    const float* __restrict__ x0, const float* __restrict__ x1,
    const float* __restrict__ x2,
    const float* __restrict__ W0, const float* __restrict__ b0,
    const float* __restrict__ W1, const float* __restrict__ b1,
    const float* __restrict__ W2, const float* __restrict__ b2,
    float* __restrict__ out0, float* __restrict__ out1, float* __restrict__ out2)
{
    int blk = blockIdx.x, tid = threadIdx.x;
    if (blk < 128) {
        // ---- out2: idx -> (pos, half); pos=(b,i,j); 8 outputs per thread ----
        __shared__ __align__(16) float sW2[64 * 16];
        for (int idx = tid; idx < 1024; idx += 256) sW2[idx] = W2[idx];
        __syncthreads();

        int idx = blk * 256 + tid;
        int half = idx & 1;
        int pos = idx >> 1;                 // b,i,j
        int j = pos & 31, i = (pos >> 5) & 31, b = pos >> 10;
        int o0 = half * 8;

        float acc[8];
        {
            const float* bb = b2 + o0;
            #pragma unroll
            for (int o = 0; o < 8; o++) acc[o] = bb[o];
        }

        // accumulate one source chunk: cnt channels starting at weight row rb
        #define ACC_SRC(PTR, RB, CNT)                                          \
            {                                                                  \
                const float* _s = (PTR);                                       \
                _Pragma("unroll")                                              \
                for (int c = 0; c < (CNT); c++) {                              \
                    float v = _s[c];                                           \
                    const float* w = sW2 + ((RB) + c) * 16 + o0;               \
                    _Pragma("unroll")                                          \
                    for (int o = 0; o < 8; o++) acc[o] += v * w[o];            \
                }                                                              \
            }

        ACC_SRC(x1 + (b * 32 + i) * 8, 0, 8);                 // x1[b,i]
        ACC_SRC(x2 + ((b * 32 + i) * 32 + j) * 8, 8, 8);      // x2[b,i,j]
        ACC_SRC(g_R3 + ((b * 32 + i) * 32 + j) * 16, 16, 16); // reduce(x3)[b,i,j]
        ACC_SRC(x1 + (b * 32 + j) * 8, 32, 8);                // x1[b,j]
        ACC_SRC(x2 + ((b * 32 + j) * 32 + i) * 8, 40, 8);     // x2[b,j,i]
        ACC_SRC(g_R3 + ((b * 32 + j) * 32 + i) * 16, 48, 16); // reduce(x3)[b,j,i]
        #undef ACC_SRC

        float* dst = out2 + (size_t)pos * 16 + o0;
        #pragma unroll
        for (int o = 0; o < 8; o++) dst[o] = sigm(acc[o]);
    } else if (blk < 144) {
        // ---- out1 for batch b: phase1 reduce(x2) -> smem, phase2 matmul ----
        int b = blk - 128;
        __shared__ float sMax[32 * 8];   // [i][c]
        __shared__ float sMin[32 * 8];
        __shared__ __align__(16) float sW1[32 * 16];
        __shared__ float sX0[8];

        for (int idx = tid; idx < 512; idx += 256) sW1[idx] = W1[idx];
        if (tid < 8) sX0[tid] = x0[b * 8 + tid];
        {
            int i = tid >> 3, c = tid & 7;
            const float* p = x2 + ((b * 32 + i) * 32) * 8 + c;
            float vmax = -INFINITY, vmin = INFINITY;
            #pragma unroll 8
            for (int a = 0; a < 32; a++) {
                float v = p[a * 8];
                float vm = (a == i) ? 0.0f : v;
                float vn = (a == i) ? 1.0f : v;
                vmax = fmaxf(vmax, vm);
                vmin = fminf(vmin, vn);
            }
            sMax[tid] = vmax;
            sMin[tid] = vmin;
        }
        __syncthreads();

        #pragma unroll
        for (int it = 0; it < 2; it++) {
            int item = tid * 2 + it;        // (i,o)
            int i = item >> 4, o = item & 15;
            float acc = b1[o];
            const float* x1i = x1 + (b * 32 + i) * 8;
            #pragma unroll
            for (int c = 0; c < 8; c++) {
                acc += sX0[c] * sW1[c * 16 + o];
                acc += x1i[c] * sW1[(8 + c) * 16 + o];
                acc += sMax[i * 8 + c] * sW1[(16 + c) * 16 + o];
                acc += sMin[i * 8 + c] * sW1[(24 + c) * 16 + o];
            }
            out1[(size_t)(b * 32 + i) * 16 + o] = sigm(acc);
        }
    } else {
        // ---- out0: thread per (b,o) ----
        int b = tid >> 4, o = tid & 15;
        float acc = b0[o];
        const float* x0b = x0 + b * 8;
        #pragma unroll
        for (int c = 0; c < 8; c++) acc += x0b[c] * W0[c * 16 + o];
        // reduce(x1): no exclusion (ndim < 4 branch)
        #pragma unroll
        for (int c = 0; c < 8; c++) {
            float vmax = -INFINITY, vmin = INFINITY;
            for (int n = 0; n < 32; n++) {
                float v = x1[(b * 32 + n) * 8 + c];
                vmax = fmaxf(vmax, v);
                vmin = fminf(vmin, v);
            }
            acc += vmax * W0[(8 + c) * 16 + o];
            acc += vmin * W0[(16 + c) * 16 + o];
        }
        out0[b * 16 + o] = sigm(acc);
    }
}

// ---------------------------------------------------------------------------
extern "C" void kernel_launch(void* const* d_in, const int* in_sizes, int n_in,
                              void* d_out, int out_size)
{
    const float* x0 = (const float*)d_in[0];
    const float* x1 = (const float*)d_in[1];
    const float* x2 = (const float*)d_in[2];
    const float* x3 = (const float*)d_in[3];
    const float* W0 = (const float*)d_in[4];
    const float* b0 = (const float*)d_in[5];
    const float* W1 = (const float*)d_in[6];
    const float* b1 = (const float*)d_in[7];
    const float* W2 = (const float*)d_in[8];
    const float* b2 = (const float*)d_in[9];
    const float* W3 = (const float*)d_in[10];
    const float* b3 = (const float*)d_in[11];

    float* out = (float*)d_out;
    float* out0 = out;                 // [16,16]            =     256
    float* out1 = out + 256;           // [16,32,16]         =    8192
    float* out2 = out + 8448;          // [16,32,32,16]      =  262144
    float* out3 = out + 270592;        // [16,32,32,32,16]   = 8388608

    k_main<<<1024, 256>>>(x2, x3, W3, b3, out3);
    k_tail<<<145, 256>>>(x0, x1, x2, W0, b0, W1, b1, W2, b2, out0, out1, out2);
}

// round 9
// speedup vs baseline: 3.3478x; 1.0661x over previous
#include <cuda_runtime.h>
#include <math.h>

// Shapes (hardcoded from reference): B=16, N=32, C=8, O=16
// d_in order: x0, x1, x2, x3, W0, b0, W1, b1, W2, b2, W3, b3
// d_out: concat(out0[16,16], out1[16,32,16], out2[16,32,32,16], out3[16,32,32,32,16])

#define NB 16
#define NN 32

// Scratch (device global — no runtime allocation)
__device__ float g_R3[NB * NN * NN * 16];   // reduce(x3): [b,a1,a2][max8|min8]

__device__ __forceinline__ float sigm(float x) {
    return __fdividef(1.0f, 1.0f + __expf(-x));
}

// Packed fp32x2 helpers (sm_100+). Per-lane rounding identical to scalar FFMA.
#define FFMA2(ACC, S, W) \
    asm("fma.rn.f32x2 %0, %1, %2, %0;" : "+l"(ACC) : "l"(S), "l"(W))
#define ADD2(D, A, B) \
    asm("add.rn.f32x2 %0, %1, %2;" : "=l"(D) : "l"(A), "l"(B))
#define PACK2(D, F) \
    asm("mov.b64 %0, {%1, %1};" : "=l"(D) : "r"(__float_as_uint(F)))
#define UNPACK2(LO, HI, A) \
    asm("mov.b64 {%0, %1}, %2;" : "=r"(LO), "=r"(HI) : "l"(A))

// ---------------------------------------------------------------------------
// Main: out3 + R3. grid = B*N = 512 CTAs (b,i), 512 threads, 175.6KB dyn smem.
// Thread: jb=tid>>5 (0..15), k=tid&31; positions j = jb*2 + {0,1} (G=2).
//
// Smem (floats): s1[a2][a3]=x3[b,i,a2,a3,:], s2[a1][a3]=x3[b,a1,i,a3,:],
//   s3[a1][a2]=x3[b,a1,a2,i,:]  (pitch 260), sX2=x2[b], sX2T=x2[b]^T,
//   sW=W3 (96x16), sA[j][o] (b3 + p0/p2 x2-terms), sC[k][o] (p1/p3 x2-terms).
//
// logit(j,k,:) = sA[j] + sC[k] + sum_{t=0..7} v_t(j,k) . Wrow(t)
//   t0..5: x3 perms from slices; t6: x2[b,j,k]·W3[64:72]; t7: x2[b,k,j]·W3[80:88]
// All math in packed f32x2 (8 u64 accumulators per position).
// ---------------------------------------------------------------------------
#define PITCH 260
#define SLICE (32 * PITCH)              // 8320
#define SM_S1 0
#define SM_S2 SLICE
#define SM_S3 (2 * SLICE)
#define SM_X2  (3 * SLICE)              // +8192
#define SM_X2T (3 * SLICE + 8192)       // +8192
#define SM_W   (3 * SLICE + 16384)      // +1536
#define SM_A   (3 * SLICE + 17920)      // +512
#define SM_C   (3 * SLICE + 18432)      // +512
#define SM_FLOATS (3 * SLICE + 18944)   // 43904 floats = 175616 bytes

__global__ void __launch_bounds__(512) k_main(
    const float* __restrict__ x2, const float* __restrict__ x3,
    const float* __restrict__ W3, const float* __restrict__ b3,
    float* __restrict__ out3)
{
    extern __shared__ __align__(16) float sm[];
    int blk = blockIdx.x;
    int b = blk >> 5;
    int i = blk & 31;
    int tid = threadIdx.x;

    const float* x3b = x3 + (size_t)b * 32 * 32 * 32 * 8;
    const float* x2b = x2 + (size_t)b * 8192;

    // ---- stage (coalesced float4 global reads) ----
    // s1: x3[b,i,:,:]
    {
        const float4* src = (const float4*)(x3b + i * 8192);
        for (int idx = tid; idx < 2048; idx += 512) {
            int r = idx >> 6, w = idx & 63;
            *(float4*)(sm + SM_S1 + r * PITCH + w * 4) = src[idx];
        }
    }
    // s2: x3[b,a,i,:]
    for (int idx = tid; idx < 2048; idx += 512) {
        int a = idx >> 6, w = idx & 63;
        float4 v = *(const float4*)(x3b + a * 8192 + i * 256 + w * 4);
        *(float4*)(sm + SM_S2 + a * PITCH + w * 4) = v;
    }
    // s3: x3[b,a1,a2,i,:]
    for (int idx = tid; idx < 2048; idx += 512) {
        int ch = idx >> 1, hf = idx & 1;
        int a1 = ch >> 5, a2 = ch & 31;
        float4 v = *(const float4*)(x3b + a1 * 8192 + a2 * 256 + i * 8 + hf * 4);
        *(float4*)(sm + SM_S3 + a1 * PITCH + a2 * 8 + hf * 4) = v;
    }
    // sX2 (natural layout) + sX2T (transposed pair order)
    for (int idx = tid; idx < 2048; idx += 512) {
        float4 v = *(const float4*)(x2b + idx * 4);
        *(float4*)(sm + SM_X2 + idx * 4) = v;
        int hf = idx & 1, kk = (idx >> 1) & 31, jj = idx >> 6;
        *(float4*)(sm + SM_X2T + (kk * 32 + jj) * 8 + hf * 4) = v;
    }
    // sW: full W3 (96x16)
    if (tid < 384) {
        ((float4*)(sm + SM_W))[tid] = ((const float4*)W3)[tid];
    }
    __syncthreads();

    // ---- sA[j][o] (incl b3), sC[k][o] ----
    {
        int j = tid >> 4, o = tid & 15;
        float accA = b3[o], accC = 0.0f;
        #pragma unroll
        for (int cc = 0; cc < 8; cc++) {
            float xij = sm[SM_X2 + (i * 32 + j) * 8 + cc];
            float xji = sm[SM_X2 + (j * 32 + i) * 8 + cc];
            accA += xij * sm[SM_W + cc * 16 + o] + xji * sm[SM_W + (32 + cc) * 16 + o];
            accC += xij * sm[SM_W + (16 + cc) * 16 + o] + xji * sm[SM_W + (48 + cc) * 16 + o];
        }
        sm[SM_A + tid] = accA;
        sm[SM_C + tid] = accC;
    }
    __syncthreads();

    // ---- R3[b,i,j,:] from s1 (masked reduce over a3, exclude a3==j) ----
    if (tid < 256) {
        int j = tid >> 3, c = tid & 7;
        const float* row = sm + SM_S1 + j * PITCH + c;
        float vmax = -INFINITY, vmin = INFINITY;
        #pragma unroll
        for (int a = 0; a < 32; a++) {
            float v = row[a * 8];
            float vm = (a == j) ? 0.0f : v;
            float vn = (a == j) ? 1.0f : v;
            vmax = fmaxf(vmax, vm);
            vmin = fminf(vmin, vn);
        }
        int o = ((b * 32 + i) * 32 + j) * 16;
        g_R3[o + c] = vmax;
        g_R3[o + 8 + c] = vmin;
    }

    // ---- main compute: 2 positions, packed f32x2 ----
    int k = tid & 31, jb = tid >> 5;
    int j0 = jb * 2;

    unsigned long long acc[2][8];
    #pragma unroll
    for (int g = 0; g < 2; g++) {
        int j = j0 + g;
        const unsigned long long* pa = (const unsigned long long*)(sm + SM_A + j * 16);
        const unsigned long long* pc = (const unsigned long long*)(sm + SM_C + k * 16);
        #pragma unroll
        for (int op = 0; op < 8; op++) {
            unsigned long long t;
            ADD2(t, pa[op], pc[op]);
            acc[g][op] = t;
        }
    }

    // per-g source offsets
    int rowoff[2], coloff[2], x2off[2];
    #pragma unroll
    for (int g = 0; g < 2; g++) {
        int j = j0 + g;
        rowoff[g] = j * PITCH + k * 8;
        coloff[g] = k * PITCH + j * 8;
        x2off[g]  = (j * 32 + k) * 8;
    }

    const int RB[8] = {8, 24, 40, 56, 72, 88, 64, 80};  // W3 row blocks per term

    #pragma unroll
    for (int t = 0; t < 8; t++) {
        // source vectors for both positions
        float v[2][8];
        #pragma unroll
        for (int g = 0; g < 2; g++) {
            const float* p;
            if (t < 6) {
                const float* sl = sm + (t >> 1) * SLICE;
                p = sl + ((t & 1) ? coloff[g] : rowoff[g]);
            } else if (t == 6) {
                p = sm + SM_X2 + x2off[g];      // x2[b,j,k]
            } else {
                p = sm + SM_X2T + x2off[g];     // x2[b,k,j]
            }
            float4 lo = *(const float4*)p;
            float4 hi = *(const float4*)(p + 4);
            v[g][0] = lo.x; v[g][1] = lo.y; v[g][2] = lo.z; v[g][3] = lo.w;
            v[g][4] = hi.x; v[g][5] = hi.y; v[g][6] = hi.z; v[g][7] = hi.w;
        }
        const float* wrow = sm + SM_W + RB[t] * 16;
        #pragma unroll
        for (int cc = 0; cc < 8; cc++) {
            const unsigned long long* w8 = (const unsigned long long*)(wrow + cc * 16);
            unsigned long long w0 = w8[0], w1 = w8[1], w2 = w8[2], w3 = w8[3];
            unsigned long long w4 = w8[4], w5 = w8[5], w6 = w8[6], w7 = w8[7];
            #pragma unroll
            for (int g = 0; g < 2; g++) {
                unsigned long long s2p;
                PACK2(s2p, v[g][cc]);
                FFMA2(acc[g][0], s2p, w0);
                FFMA2(acc[g][1], s2p, w1);
                FFMA2(acc[g][2], s2p, w2);
                FFMA2(acc[g][3], s2p, w3);
                FFMA2(acc[g][4], s2p, w4);
                FFMA2(acc[g][5], s2p, w5);
                FFMA2(acc[g][6], s2p, w6);
                FFMA2(acc[g][7], s2p, w7);
            }
        }
    }

    // ---- sigmoid + store ----
    #pragma unroll
    for (int g = 0; g < 2; g++) {
        int j = j0 + g;
        float r[16];
        #pragma unroll
        for (int op = 0; op < 8; op++) {
            unsigned int lo, hi;
            UNPACK2(lo, hi, acc[g][op]);
            r[op * 2 + 0] = sigm(__uint_as_float(lo));
            r[op * 2 + 1] = sigm(__uint_as_float(hi));
        }
        float4* dst = (float4*)(out3 + ((((size_t)b * 32 + i) * 32 + j) * 32 + k) * 16);
        dst[0] = make_float4(r[0], r[1], r[2], r[3]);
        dst[1] = make_float4(r[4], r[5], r[6], r[7]);
        dst[2] = make_float4(r[8], r[9], r[10], r[11]);
        dst[3] = make_float4(r[12], r[13], r[14], r[15]);
    }
}

// ---------------------------------------------------------------------------
// Tail (unchanged from R8, 9.9us measured):
//   blocks [0,128): out2 — 2 threads per (b,i,j), 8 outputs each
//   blocks [128,144): out1 — one CTA per b
//   block 144: out0
// ---------------------------------------------------------------------------
__global__ void __launch_bounds__(256) k_tail(
    const float* __restrict__ x0, const float* __restrict__ x1,
    const float* __restrict__ x2,
    const float* __restrict__ W0, const float* __restrict__ b0,
    const float* __restrict__ W1, const float* __restrict__ b1,
    const float* __restrict__ W2, const float* __restrict__ b2,
    float* __restrict__ out0, float* __restrict__ out1, float* __restrict__ out2)
{
    int blk = blockIdx.x, tid = threadIdx.x;
    if (blk < 128) {
        __shared__ __align__(16) float sW2[64 * 16];
        for (int idx = tid; idx < 1024; idx += 256) sW2[idx] = W2[idx];
        __syncthreads();

        int idx = blk * 256 + tid;
        int half = idx & 1;
        int pos = idx >> 1;                 // b,i,j
        int j = pos & 31, i = (pos >> 5) & 31, b = pos >> 10;
        int o0 = half * 8;

        float acc[8];
        {
            const float* bb = b2 + o0;
            #pragma unroll
            for (int o = 0; o < 8; o++) acc[o] = bb[o];
        }

        #define ACC_SRC(PTR, RB_, CNT)                                         \
            {                                                                  \
                const float* _s = (PTR);                                       \
                _Pragma("unroll")                                              \
                for (int c = 0; c < (CNT); c++) {                              \
                    float v = _s[c];                                           \
                    const float* w = sW2 + ((RB_) + c) * 16 + o0;              \
                    _Pragma("unroll")                                          \
                    for (int o = 0; o < 8; o++) acc[o] += v * w[o];            \
                }                                                              \
            }

        ACC_SRC(x1 + (b * 32 + i) * 8, 0, 8);
        ACC_SRC(x2 + ((b * 32 + i) * 32 + j) * 8, 8, 8);
        ACC_SRC(g_R3 + ((b * 32 + i) * 32 + j) * 16, 16, 16);
        ACC_SRC(x1 + (b * 32 + j) * 8, 32, 8);
        ACC_SRC(x2 + ((b * 32 + j) * 32 + i) * 8, 40, 8);
        ACC_SRC(g_R3 + ((b * 32 + j) * 32 + i) * 16, 48, 16);
        #undef ACC_SRC

        float* dst = out2 + (size_t)pos * 16 + o0;
        #pragma unroll
        for (int o = 0; o < 8; o++) dst[o] = sigm(acc[o]);
    } else if (blk < 144) {
        int b = blk - 128;
        __shared__ float sMax[32 * 8];
        __shared__ float sMin[32 * 8];
        __shared__ __align__(16) float sW1[32 * 16];
        __shared__ float sX0[8];

        for (int idx = tid; idx < 512; idx += 256) sW1[idx] = W1[idx];
        if (tid < 8) sX0[tid] = x0[b * 8 + tid];
        {
            int i = tid >> 3, c = tid & 7;
            const float* p = x2 + ((b * 32 + i) * 32) * 8 + c;
            float vmax = -INFINITY, vmin = INFINITY;
            #pragma unroll 8
            for (int a = 0; a < 32; a++) {
                float v = p[a * 8];
                float vm = (a == i) ? 0.0f : v;
                float vn = (a == i) ? 1.0f : v;
                vmax = fmaxf(vmax, vm);
                vmin = fminf(vmin, vn);
            }
            sMax[tid] = vmax;
            sMin[tid] = vmin;
        }
        __syncthreads();

        #pragma unroll
        for (int it = 0; it < 2; it++) {
            int item = tid * 2 + it;
            int i = item >> 4, o = item & 15;
            float acc = b1[o];
            const float* x1i = x1 + (b * 32 + i) * 8;
            #pragma unroll
            for (int c = 0; c < 8; c++) {
                acc += sX0[c] * sW1[c * 16 + o];
                acc += x1i[c] * sW1[(8 + c) * 16 + o];
                acc += sMax[i * 8 + c] * sW1[(16 + c) * 16 + o];
                acc += sMin[i * 8 + c] * sW1[(24 + c) * 16 + o];
            }
            out1[(size_t)(b * 32 + i) * 16 + o] = sigm(acc);
        }
    } else {
        int b = tid >> 4, o = tid & 15;
        float acc = b0[o];
        const float* x0b = x0 + b * 8;
        #pragma unroll
        for (int c = 0; c < 8; c++) acc += x0b[c] * W0[c * 16 + o];
        #pragma unroll
        for (int c = 0; c < 8; c++) {
            float vmax = -INFINITY, vmin = INFINITY;
            for (int n = 0; n < 32; n++) {
                float v = x1[(b * 32 + n) * 8 + c];
                vmax = fmaxf(vmax, v);
                vmin = fminf(vmin, v);
            }
            acc += vmax * W0[(8 + c) * 16 + o];
            acc += vmin * W0[(16 + c) * 16 + o];
        }
        out0[b * 16 + o] = sigm(acc);
    }
}

// ---------------------------------------------------------------------------
extern "C" void kernel_launch(void* const* d_in, const int* in_sizes, int n_in,
                              void* d_out, int out_size)
{
    const float* x0 = (const float*)d_in[0];
    const float* x1 = (const float*)d_in[1];
    const float* x2 = (const float*)d_in[2];
    const float* x3 = (const float*)d_in[3];
    const float* W0 = (const float*)d_in[4];
    const float* b0 = (const float*)d_in[5];
    const float* W1 = (const float*)d_in[6];
    const float* b1 = (const float*)d_in[7];
    const float* W2 = (const float*)d_in[8];
    const float* b2 = (const float*)d_in[9];
    const float* W3 = (const float*)d_in[10];
    const float* b3 = (const float*)d_in[11];

    float* out = (float*)d_out;
    float* out0 = out;                 // [16,16]            =     256
    float* out1 = out + 256;           // [16,32,16]         =    8192
    float* out2 = out + 8448;          // [16,32,32,16]      =  262144
    float* out3 = out + 270592;        // [16,32,32,32,16]   = 8388608

    const int smem_bytes = SM_FLOATS * 4;  // 175616
    cudaFuncSetAttribute(k_main, cudaFuncAttributeMaxDynamicSharedMemorySize, smem_bytes);

    k_main<<<512, 512, smem_bytes>>>(x2, x3, W3, b3, out3);
    k_tail<<<145, 256>>>(x0, x1, x2, W0, b0, W1, b1, W2, b2, out0, out1, out2);
}